// round 6
// baseline (speedup 1.0000x reference)
#include <cuda_runtime.h>
#include <math.h>

// Problem: B=2, N=1024, T=12, H=64, F=1
#define NB 1024
#define IMP_OFF  0
#define PRED_OFF 24576
#define REP_OFF  49152

// ---------------- persistent scratch (device globals; no runtime allocation) ------
__device__ __align__(16) float g_h   [2*64*NB];   // hidden state (B,H,N)
__device__ __align__(16) float g_E64 [4*64*NB];   // A_sb h
__device__ __align__(16) float g_F64 [4*64*NB];   // A_sb^2 h
__device__ __align__(16) float g_G64 [4*64*NB];   // A_sb (r*h)
__device__ __align__(16) float g_H64 [4*64*NB];   // A_sb^2 (r*h)
__device__ __align__(16) float g_Dx  [4*2*NB];    // A_sb [x1;m]
__device__ __align__(16) float g_Ex  [4*2*NB];    // A_sb [x2;m]
__device__ __align__(16) float g_Fx  [4*2*NB];    // A_sb^2 [x2;m]
__device__ __align__(16) float g_u   [2*64*NB];   // update gate
__device__ __align__(16) float g_rh  [2*64*NB];   // r*h
__device__ __align__(16) float g_z1  [2*2*NB];    // [x1 ; m]  (B,2,N)
__device__ __align__(16) float g_z2  [2*2*NB];    // [x2 ; m]  (B,2,N)
__device__ __align__(16) float g_rs  [4*NB];      // rowsums of A_sb
__device__ __align__(16) float g_rep [12*2*128*NB]; // staged representations (t,b,2H,N)
// transposed weights [k][c]
__device__ __align__(16) float g_Wlout_t[128*64];
__device__ __align__(16) float g_Wr_t   [330*64];
__device__ __align__(16) float g_Wu_t   [330*64];
__device__ __align__(16) float g_Wc_t   [330*64];
__device__ __align__(16) float g_M_t    [2*66*64];  // (Wgc_s @ Wdin)^T  [s][j][c]
__device__ __align__(16) float g_vb     [2*64];     // Wgc_s @ bdin

__global__ void init_h_kernel()
{
    int i = blockIdx.x * 256 + threadIdx.x;
    if (i < 2*64*NB) g_h[i] = 0.f;
}

__global__ void prep_weights_kernel(const float* __restrict__ Wr,
                                    const float* __restrict__ Wu,
                                    const float* __restrict__ Wc,
                                    const float* __restrict__ Wlout)
{
    int idx = blockIdx.x * 256 + threadIdx.x;
    if (idx >= 330*64) return;
    int j = idx >> 6;     // k (column of original)
    int i = idx & 63;     // c (row of original)
    g_Wr_t[idx] = Wr[i*330 + j];
    g_Wu_t[idx] = Wu[i*330 + j];
    g_Wc_t[idx] = Wc[i*330 + j];
    if (j < 128) g_Wlout_t[idx] = Wlout[i*128 + j];
}

// M_s = Wgc[:, s*64:(s+1)*64] @ Wdin  (64x66), stored transposed [j][c]
// vb_s = Wgc_s @ bdin
__global__ void prep_M_kernel(const float* __restrict__ Wgc,
                              const float* __restrict__ Wdin,
                              const float* __restrict__ bdin)
{
    const int s = blockIdx.y;
    int idx = blockIdx.x * 256 + threadIdx.x;
    if (idx < 66*64) {
        int j = idx >> 6, c = idx & 63;
        float acc = 0.f;
        for (int k = 0; k < 64; k++)
            acc += Wgc[c*128 + s*64 + k] * Wdin[k*66 + j];
        g_M_t[s*66*64 + idx] = acc;
    } else if (idx < 66*64 + 64) {
        int c = idx - 66*64;
        float acc = 0.f;
        for (int k = 0; k < 64; k++)
            acc += Wgc[c*128 + s*64 + k] * bdin[k];
        g_vb[s*64 + c] = acc;
    }
}

// rowsums: g_rs[sb][w] = sum_v A[sb][w][v]
__global__ __launch_bounds__(256) void rowsum_kernel(const float* __restrict__ adj)
{
    const int sb = blockIdx.y;
    const int warp = threadIdx.x >> 5, lane = threadIdx.x & 31;
    const int w = blockIdx.x * 8 + warp;
    const float* Arow = adj + (size_t)sb*1048576 + (size_t)w*1024;
    float a = 0.f;
    #pragma unroll
    for (int j = 0; j < 8; j++) {
        float4 av = *(const float4*)&Arow[lane*4 + j*128];
        a += av.x + av.y + av.z + av.w;
    }
    #pragma unroll
    for (int off = 16; off; off >>= 1) a += __shfl_down_sync(0xffffffffu, a, off);
    if (lane == 0) g_rs[sb*1024 + w] = a;
}

// =====================================================================================
// Big diffusion: O[sb][c][w] = sum_v Z[.][c][v] * A[sb][w][v]
// BM=32(ch) x BN=32(w) x BK=32, 256 threads, grid (32,2,4)=256 blocks, 2 blocks/SM.
// Warp = 4 channels (broadcast float4 Z) x 32 w (scalar A).
// stage 0: h->E  1: E->F  2: rh->G  3: G->H
// =====================================================================================
__global__ __launch_bounds__(256) void diffuse64_kernel(const float* __restrict__ adj, int stage)
{
    const int sb = blockIdx.z;
    const int c0 = blockIdx.y * 32;
    const int w0 = blockIdx.x * 32;
    const float* Z; float* O;
    switch (stage) {
        case 0:  Z = g_h   + (sb&1)*65536; O = g_E64 + sb*65536; break;
        case 1:  Z = g_E64 + sb*65536;     O = g_F64 + sb*65536; break;
        case 2:  Z = g_rh  + (sb&1)*65536; O = g_G64 + sb*65536; break;
        default: Z = g_G64 + sb*65536;     O = g_H64 + sb*65536; break;
    }
    const float* A = adj + (size_t)sb*1048576 + (size_t)w0*1024;
    const int tid = threadIdx.x;

    __shared__ float Zs[2][32][36];   // [k][c], stride 36 (16B-aligned rows)
    __shared__ float As[2][32][33];   // [k][w], stride 33 (conflict-free STS)

    const int lr = tid >> 3;          // 0..31 row (channel for Z, w for A)
    const int lv = (tid & 7) * 4;     // v offset (one float4)

    const float* Zrow = Z + (size_t)(c0 + lr)*1024;
    const float* Arow = A + (size_t)lr*1024;

    float4 rz, ra;
    rz = *(const float4*)&Zrow[lv];
    ra = *(const float4*)&Arow[lv];
    Zs[0][lv+0][lr] = rz.x; Zs[0][lv+1][lr] = rz.y;
    Zs[0][lv+2][lr] = rz.z; Zs[0][lv+3][lr] = rz.w;
    As[0][lv+0][lr] = ra.x; As[0][lv+1][lr] = ra.y;
    As[0][lv+2][lr] = ra.z; As[0][lv+3][lr] = ra.w;
    __syncthreads();

    const int cg   = (tid >> 5) * 4;  // warp channel group (broadcast within warp)
    const int lane = tid & 31;        // w
    float acc[4] = {};

    int buf = 0;
    for (int kt = 0; kt < 32; kt++) {
        if (kt < 31) {
            const int v0 = (kt + 1) * 32;
            rz = *(const float4*)&Zrow[v0 + lv];
            ra = *(const float4*)&Arow[v0 + lv];
        }
        #pragma unroll
        for (int k = 0; k < 32; k++) {
            float4 z = *(const float4*)&Zs[buf][k][cg];   // warp broadcast
            float  a = As[buf][k][lane];
            acc[0] += z.x*a; acc[1] += z.y*a;
            acc[2] += z.z*a; acc[3] += z.w*a;
        }
        if (kt < 31) {
            const int nb2 = buf ^ 1;
            Zs[nb2][lv+0][lr] = rz.x; Zs[nb2][lv+1][lr] = rz.y;
            Zs[nb2][lv+2][lr] = rz.z; Zs[nb2][lv+3][lr] = rz.w;
            As[nb2][lv+0][lr] = ra.x; As[nb2][lv+1][lr] = ra.y;
            As[nb2][lv+2][lr] = ra.z; As[nb2][lv+3][lr] = ra.w;
        }
        __syncthreads();
        buf ^= 1;
    }
    #pragma unroll
    for (int i = 0; i < 4; i++) {
        O[(size_t)(c0+cg+i)*1024 + w0 + lane] = acc[i];
    }
}

// =====================================================================================
// 2-channel diffusion. stage 0: z1->Dx  1: z2->Ex  2: Ex->Fx
// grid (128, 4), 256 threads: one w per warp, float4 lanes over v (MLP 8) + warp reduce.
// =====================================================================================
__global__ __launch_bounds__(256) void diffuse2_kernel(const float* __restrict__ adj, int stage)
{
    const int sb = blockIdx.y;
    __shared__ float zs[2][NB];
    const float* src;
    if      (stage == 0) src = g_z1 + (sb&1)*2048;
    else if (stage == 1) src = g_z2 + (sb&1)*2048;
    else                 src = g_Ex + sb*2048;
    for (int i = threadIdx.x; i < 2048; i += 256) zs[i >> 10][i & 1023] = src[i];
    __syncthreads();

    const int warp = threadIdx.x >> 5, lane = threadIdx.x & 31;
    const int w = blockIdx.x * 8 + warp;
    const float* Arow = adj + (size_t)sb*1048576 + (size_t)w*1024;
    float a0 = 0.f, a1 = 0.f;
    #pragma unroll
    for (int j = 0; j < 8; j++) {
        const int v = lane*4 + j*128;
        float4 av = *(const float4*)&Arow[v];
        float4 z0 = *(const float4*)&zs[0][v];
        float4 z1 = *(const float4*)&zs[1][v];
        a0 += av.x*z0.x + av.y*z0.y + av.z*z0.z + av.w*z0.w;
        a1 += av.x*z1.x + av.y*z1.y + av.z*z1.z + av.w*z1.w;
    }
    #pragma unroll
    for (int off = 16; off; off >>= 1) {
        a0 += __shfl_down_sync(0xffffffffu, a0, off);
        a1 += __shfl_down_sync(0xffffffffu, a1, off);
    }
    if (lane == 0) {
        float* dst;
        if      (stage == 0) dst = g_Dx + sb*2048;
        else if (stage == 1) dst = g_Ex + sb*2048;
        else                 dst = g_Fx + sb*2048;
        dst[w]        = a0;
        dst[1024 + w] = a1;
    }
}

// =====================================================================================
// pre kernel: xs1 = Wfs.h + bfs ; preds out ; x1 = m?x:xs1 ; z1 = [x1;m]
// =====================================================================================
__global__ __launch_bounds__(32) void pre_kernel(const float* __restrict__ x,
                                                 const int*   __restrict__ mask,
                                                 const float* __restrict__ Wfs,
                                                 const float* __restrict__ bfs,
                                                 float* __restrict__ out, int t)
{
    const int b  = blockIdx.x >> 5;
    const int nn = (blockIdx.x & 31) * 32 + threadIdx.x;
    float s = bfs[0];
    #pragma unroll 8
    for (int c = 0; c < 64; c++) s += Wfs[c] * g_h[b*65536 + c*1024 + nn];
    out[PRED_OFF + (b*1024 + nn)*12 + t] = s;
    int m = mask[b*12288 + nn*12 + t];
    float xv = x[b*12288 + nn*12 + t];
    float x1 = m ? xv : s;
    g_z1[b*2048 + nn]        = x1;
    g_z1[b*2048 + 1024 + nn] = (float)m;
}

// =====================================================================================
// decoder (16-wide n-tiles, 128 blocks):
//   out = M0.[Dx0;E0] + M1.[Dx1;E1] + vb0*rs0 + vb1*rs1 + bgc
//   out = prelu(Wlout.[out;h]+blout) ; repr=[out;h] ; xs2=Wro.repr+bro
//   imps out ; z2 = [m?x1:xs2 ; m]
// =====================================================================================
__global__ __launch_bounds__(256) void decoder_kernel(const float* __restrict__ bgc,
                                                      const float* __restrict__ blout,
                                                      const float* __restrict__ Wro,
                                                      const float* __restrict__ bro,
                                                      const float* __restrict__ prelu_a,
                                                      const int*   __restrict__ mask,
                                                      float* __restrict__ out, int t)
{
    const int b  = blockIdx.x >> 6;
    const int n0 = (blockIdx.x & 63) * 16;
    const int tid = threadIdx.x;
    __shared__ float E0s[64][17];
    __shared__ float E1s[64][17];
    __shared__ float Hs[64][17];
    __shared__ float Gs[64][17];
    __shared__ float Os[64][17];
    __shared__ float DXs[2][2][17];
    __shared__ float RSs[2][17];

    for (int i = tid; i < 64*16; i += 256) {
        int r = i >> 4, n = i & 15;
        E0s[r][n] = g_E64[b*65536     + r*1024 + n0 + n];
        E1s[r][n] = g_E64[(2+b)*65536 + r*1024 + n0 + n];
        Hs[r][n]  = g_h  [b*65536     + r*1024 + n0 + n];
    }
    if (tid < 64) {
        int s = tid >> 5, ch = (tid >> 4) & 1, n = tid & 15;
        DXs[s][ch][n] = g_Dx[(s*2 + b)*2048 + ch*1024 + n0 + n];
    } else if (tid < 96) {
        int idx = tid - 64; int s = idx >> 4, n = idx & 15;
        RSs[s][n] = g_rs[(s*2 + b)*1024 + n0 + n];
    }
    __syncthreads();

    const int ty = tid >> 4, tx = tid & 15;
    const int cbv = ty*4;
    float acc[4] = {};
    #pragma unroll
    for (int s = 0; s < 2; s++) {
        const float* Mt = g_M_t + s*66*64;
        {
            float4 w0 = *(const float4*)&Mt[0*64 + cbv];
            float v0 = DXs[s][0][tx];
            acc[0] += w0.x*v0; acc[1] += w0.y*v0; acc[2] += w0.z*v0; acc[3] += w0.w*v0;
            float4 w1 = *(const float4*)&Mt[1*64 + cbv];
            float v1 = DXs[s][1][tx];
            acc[0] += w1.x*v1; acc[1] += w1.y*v1; acc[2] += w1.z*v1; acc[3] += w1.w*v1;
        }
        #pragma unroll 4
        for (int k = 0; k < 64; k++) {
            float4 w = *(const float4*)&Mt[(2+k)*64 + cbv];
            float v = s ? E1s[k][tx] : E0s[k][tx];
            acc[0] += w.x*v; acc[1] += w.y*v; acc[2] += w.z*v; acc[3] += w.w*v;
        }
    }
    #pragma unroll
    for (int i = 0; i < 4; i++) {
        int c = cbv + i;
        Gs[c][tx] = acc[i] + g_vb[c]*RSs[0][tx] + g_vb[64+c]*RSs[1][tx] + bgc[c];
    }
    __syncthreads();

    float acc2[4] = {};
    #pragma unroll 4
    for (int k = 0; k < 64; k++) {
        float4 w = *(const float4*)&g_Wlout_t[k*64 + cbv];
        float v = Gs[k][tx];
        acc2[0] += w.x*v; acc2[1] += w.y*v; acc2[2] += w.z*v; acc2[3] += w.w*v;
    }
    #pragma unroll 4
    for (int k = 0; k < 64; k++) {
        float4 w = *(const float4*)&g_Wlout_t[(64+k)*64 + cbv];
        float v = Hs[k][tx];
        acc2[0] += w.x*v; acc2[1] += w.y*v; acc2[2] += w.z*v; acc2[3] += w.w*v;
    }
    const float pa = prelu_a[0];
    #pragma unroll
    for (int i = 0; i < 4; i++) {
        int c = cbv + i;
        float o = acc2[i] + blout[c]; if (o < 0.f) o *= pa;
        Os[c][tx] = o;
        g_rep[((size_t)(t*2 + b)*128 + c)*1024 + n0 + tx] = o;
    }
    __syncthreads();

    for (int i = tid; i < 64*16; i += 256) {
        int c = i >> 4, n = i & 15;
        g_rep[((size_t)(t*2 + b)*128 + 64 + c)*1024 + n0 + n] = Hs[c][n];
    }
    if (tid < 16) {
        const int n = tid, nn = n0 + n;
        float s = bro[0];
        #pragma unroll 8
        for (int c = 0; c < 64; c++) s += Wro[c]*Os[c][n] + Wro[64+c]*Hs[c][n];
        out[IMP_OFF + (b*1024 + nn)*12 + t] = s;
        int m = mask[b*12288 + nn*12 + t];
        float x2 = m ? g_z1[b*2048 + nn] : s;
        g_z2[b*2048 + nn]        = x2;
        g_z2[b*2048 + 1024 + nn] = (float)m;
    }
}

// =====================================================================================
// V330 loader (16-wide n-tile). base64: h or rh.
// Row map (330): [z2(2), base64(64)] , per support s: [ex(2), d1(64), fx(2), d2(64)]
// =====================================================================================
__device__ __forceinline__ void load_V330_16(float (*Vs)[17], int b, int n0, int tid,
                                             const float* base64)
{
    for (int i = tid; i < 330*16; i += 256) {
        int r = i >> 4, n = i & 15;
        const float* src;
        const int sb0 = b, sb1 = 2 + b;
        if      (r < 2)   src = g_z2   + b*2048    + r*1024;
        else if (r < 66)  src = base64 + b*65536   + (r-2)*1024;
        else if (r < 68)  src = g_Ex   + sb0*2048  + (r-66)*1024;
        else if (r < 132) src = (base64 == g_h ? g_E64 : g_G64) + sb0*65536 + (r-68)*1024;
        else if (r < 134) src = g_Fx   + sb0*2048  + (r-132)*1024;
        else if (r < 198) src = (base64 == g_h ? g_F64 : g_H64) + sb0*65536 + (r-134)*1024;
        else if (r < 200) src = g_Ex   + sb1*2048  + (r-198)*1024;
        else if (r < 264) src = (base64 == g_h ? g_E64 : g_G64) + sb1*65536 + (r-200)*1024;
        else if (r < 266) src = g_Fx   + sb1*2048  + (r-264)*1024;
        else              src = (base64 == g_h ? g_F64 : g_H64) + sb1*65536 + (r-266)*1024;
        Vs[r][n] = src[n0 + n];
    }
}

__global__ __launch_bounds__(256) void gates_kernel(const float* __restrict__ br,
                                                    const float* __restrict__ bu)
{
    const int b  = blockIdx.x >> 6;
    const int n0 = (blockIdx.x & 63) * 16;
    const int tid = threadIdx.x;
    __shared__ float Vs[330][17];
    load_V330_16(Vs, b, n0, tid, g_h);
    __syncthreads();

    const int ty = tid >> 4, tx = tid & 15;
    const int cbv = ty*4;
    float ar4[4] = {}, au4[4] = {};
    #pragma unroll 5
    for (int k = 0; k < 330; k++) {
        float4 wr = *(const float4*)&g_Wr_t[k*64 + cbv];
        float4 wu = *(const float4*)&g_Wu_t[k*64 + cbv];
        float v = Vs[k][tx];
        ar4[0] += wr.x*v; ar4[1] += wr.y*v; ar4[2] += wr.z*v; ar4[3] += wr.w*v;
        au4[0] += wu.x*v; au4[1] += wu.y*v; au4[2] += wu.z*v; au4[3] += wu.w*v;
    }
    #pragma unroll
    for (int i = 0; i < 4; i++) {
        const int c = cbv + i;
        const size_t idx = (size_t)b*65536 + c*1024 + n0 + tx;
        float hv = g_h[idx];
        float r = 1.f / (1.f + expf(-(ar4[i] + br[c])));
        float u = 1.f / (1.f + expf(-(au4[i] + bu[c])));
        g_u [idx] = u;
        g_rh[idx] = r * hv;
    }
}

__global__ __launch_bounds__(256) void cand_kernel(const float* __restrict__ bc)
{
    const int b  = blockIdx.x >> 6;
    const int n0 = (blockIdx.x & 63) * 16;
    const int tid = threadIdx.x;
    __shared__ float Vs[330][17];
    load_V330_16(Vs, b, n0, tid, g_rh);
    __syncthreads();

    const int ty = tid >> 4, tx = tid & 15;
    const int cbv = ty*4;
    float acc4[4] = {};
    #pragma unroll 5
    for (int k = 0; k < 330; k++) {
        float4 w = *(const float4*)&g_Wc_t[k*64 + cbv];
        float v = Vs[k][tx];
        acc4[0] += w.x*v; acc4[1] += w.y*v; acc4[2] += w.z*v; acc4[3] += w.w*v;
    }
    #pragma unroll
    for (int i = 0; i < 4; i++) {
        const int c = cbv + i;
        const size_t idx = (size_t)b*65536 + c*1024 + n0 + tx;
        float hv = g_h[idx];
        float uv = g_u[idx];
        float cv = tanhf(acc4[i] + bc[c]);
        g_h[idx] = uv*hv + (1.f-uv)*cv;
    }
}

// Final transpose of staged representations: out[b][cc][n][t] = g_rep[t][b][cc][n]
__global__ __launch_bounds__(256) void rep_out_kernel(float* __restrict__ out)
{
    const int bc = blockIdx.x;               // 0..255 = b*128+cc
    const int b = bc >> 7, cc = bc & 127;
    __shared__ float s[12][NB];
    for (int i = threadIdx.x; i < 12*NB; i += 256) {
        int t = i >> 10, n = i & 1023;
        s[t][n] = g_rep[((size_t)(t*2 + b)*128 + cc)*1024 + n];
    }
    __syncthreads();
    float* dst = out + REP_OFF + (size_t)bc * 12288;
    for (int i = threadIdx.x; i < 12288; i += 256) {
        int n = i / 12, t = i - n*12;
        dst[i] = s[t][n];
    }
}

extern "C" void kernel_launch(void* const* d_in, const int* in_sizes, int n_in,
                              void* d_out, int out_size)
{
    const float* x     = (const float*)d_in[0];
    const int*   mask  = (const int*)  d_in[1];
    const float* adj   = (const float*)d_in[2];
    const float* Wr    = (const float*)d_in[3];
    const float* br    = (const float*)d_in[4];
    const float* Wu    = (const float*)d_in[5];
    const float* bu    = (const float*)d_in[6];
    const float* Wc    = (const float*)d_in[7];
    const float* bc    = (const float*)d_in[8];
    const float* Wfs   = (const float*)d_in[9];
    const float* bfs   = (const float*)d_in[10];
    const float* Wdin  = (const float*)d_in[11];
    const float* bdin  = (const float*)d_in[12];
    const float* Wgc   = (const float*)d_in[13];
    const float* bgc   = (const float*)d_in[14];
    const float* Wlout = (const float*)d_in[15];
    const float* blout = (const float*)d_in[16];
    const float* Wro   = (const float*)d_in[17];
    const float* bro   = (const float*)d_in[18];
    const float* pa    = (const float*)d_in[19];
    float* out = (float*)d_out;

    init_h_kernel<<<512, 256>>>();
    prep_weights_kernel<<<83, 256>>>(Wr, Wu, Wc, Wlout);
    prep_M_kernel<<<dim3(17,2), 256>>>(Wgc, Wdin, bdin);

    for (int t = 0; t < 12; t++) {
        pre_kernel<<<64, 32>>>(x, mask, Wfs, bfs, out, t);
        diffuse2_kernel<<<dim3(128,4), 256>>>(adj, 0);          // Dx
        diffuse64_kernel<<<dim3(32,2,4), 256>>>(adj, 0);        // E = A h
        diffuse64_kernel<<<dim3(32,2,4), 256>>>(adj, 1);        // F = A E
        if (t == 0) rowsum_kernel<<<dim3(128,4), 256>>>(adj);   // loop-invariant
        decoder_kernel<<<128, 256>>>(bgc, blout, Wro, bro, pa, mask, out, t);
        diffuse2_kernel<<<dim3(128,4), 256>>>(adj, 1);          // Ex
        diffuse2_kernel<<<dim3(128,4), 256>>>(adj, 2);          // Fx
        gates_kernel<<<128, 256>>>(br, bu);
        diffuse64_kernel<<<dim3(32,2,4), 256>>>(adj, 2);        // G = A rh
        diffuse64_kernel<<<dim3(32,2,4), 256>>>(adj, 3);        // H = A G
        cand_kernel<<<128, 256>>>(bc);
    }
    rep_out_kernel<<<256, 256>>>(out);
}

// round 7
// speedup vs baseline: 1.1474x; 1.1474x over previous
#include <cuda_runtime.h>
#include <math.h>

// Problem: B=2, N=1024, T=12, H=64, F=1
#define NB 1024
#define IMP_OFF  0
#define PRED_OFF 24576
#define REP_OFF  49152

// ---------------- persistent scratch (device globals; no runtime allocation) ------
__device__ __align__(16) float g_h   [2*64*NB];   // hidden state (B,H,N)
__device__ __align__(16) float g_E64 [4*64*NB];   // A_sb h
__device__ __align__(16) float g_F64 [4*64*NB];   // A_sb^2 h
__device__ __align__(16) float g_G64 [4*64*NB];   // A_sb (r*h)
__device__ __align__(16) float g_H64 [4*64*NB];   // A_sb^2 (r*h)
__device__ __align__(16) float g_Dx  [4*2*NB];    // A_sb [x1;m]
__device__ __align__(16) float g_Ex  [4*2*NB];    // A_sb [x2;m]
__device__ __align__(16) float g_Fx  [4*2*NB];    // A_sb^2 [x2;m]
__device__ __align__(16) float g_u   [2*64*NB];   // update gate
__device__ __align__(16) float g_rh  [2*64*NB];   // r*h
__device__ __align__(16) float g_z1  [2*2*NB];    // [x1 ; m]  (B,2,N)
__device__ __align__(16) float g_z2  [2*2*NB];    // [x2 ; m]  (B,2,N)
__device__ __align__(16) float g_rs  [4*NB];      // rowsums of A_sb
__device__ __align__(16) float g_rep [12*2*128*NB]; // staged representations (t,b,2H,N)
// transposed weights [k][c]
__device__ __align__(16) float g_Wlout_t[128*64];
__device__ __align__(16) float g_Wr_t   [330*64];
__device__ __align__(16) float g_Wu_t   [330*64];
__device__ __align__(16) float g_Wc_t   [330*64];
__device__ __align__(16) float g_M_t    [2*66*64];  // (Wgc_s @ Wdin)^T  [s][j][c]
__device__ __align__(16) float g_vb     [2*64];     // Wgc_s @ bdin

__global__ void init_h_kernel()
{
    int i = blockIdx.x * 256 + threadIdx.x;
    if (i < 2*64*NB) g_h[i] = 0.f;
}

__global__ void prep_weights_kernel(const float* __restrict__ Wr,
                                    const float* __restrict__ Wu,
                                    const float* __restrict__ Wc,
                                    const float* __restrict__ Wlout)
{
    int idx = blockIdx.x * 256 + threadIdx.x;
    if (idx >= 330*64) return;
    int j = idx >> 6;     // k (column of original)
    int i = idx & 63;     // c (row of original)
    g_Wr_t[idx] = Wr[i*330 + j];
    g_Wu_t[idx] = Wu[i*330 + j];
    g_Wc_t[idx] = Wc[i*330 + j];
    if (j < 128) g_Wlout_t[idx] = Wlout[i*128 + j];
}

// M_s = Wgc[:, s*64:(s+1)*64] @ Wdin  (64x66), stored transposed [j][c]
// vb_s = Wgc_s @ bdin
__global__ void prep_M_kernel(const float* __restrict__ Wgc,
                              const float* __restrict__ Wdin,
                              const float* __restrict__ bdin)
{
    const int s = blockIdx.y;
    int idx = blockIdx.x * 256 + threadIdx.x;
    if (idx < 66*64) {
        int j = idx >> 6, c = idx & 63;
        float acc = 0.f;
        for (int k = 0; k < 64; k++)
            acc += Wgc[c*128 + s*64 + k] * Wdin[k*66 + j];
        g_M_t[s*66*64 + idx] = acc;
    } else if (idx < 66*64 + 64) {
        int c = idx - 66*64;
        float acc = 0.f;
        for (int k = 0; k < 64; k++)
            acc += Wgc[c*128 + s*64 + k] * bdin[k];
        g_vb[s*64 + c] = acc;
    }
}

// rowsums: g_rs[sb][w] = sum_v A[sb][w][v]
__global__ __launch_bounds__(256) void rowsum_kernel(const float* __restrict__ adj)
{
    const int sb = blockIdx.y;
    const int warp = threadIdx.x >> 5, lane = threadIdx.x & 31;
    const int w = blockIdx.x * 8 + warp;
    const float* Arow = adj + (size_t)sb*1048576 + (size_t)w*1024;
    float a = 0.f;
    #pragma unroll
    for (int j = 0; j < 8; j++) {
        float4 av = *(const float4*)&Arow[lane*4 + j*128];
        a += av.x + av.y + av.z + av.w;
    }
    #pragma unroll
    for (int off = 16; off; off >>= 1) a += __shfl_down_sync(0xffffffffu, a, off);
    if (lane == 0) g_rs[sb*1024 + w] = a;
}

// =====================================================================================
// Big diffusion (R5 tile — best measured): O[sb][c][w] = sum_v Z[.][c][v] * A[sb][w][v]
// BM=32(ch) x BN=64(w) x BK=32, 256 threads, grid (16,2,4)=128 blocks.
// Per warp: 4 channels via BROADCAST float4 Z read + 64 w via float2 A read.
// stage 0: h->E  1: E->F  2: rh->G  3: G->H
// =====================================================================================
__global__ __launch_bounds__(256) void diffuse64_kernel(const float* __restrict__ adj, int stage)
{
    const int sb = blockIdx.z;
    const int c0 = blockIdx.y * 32;
    const int w0 = blockIdx.x * 64;
    const float* Z; float* O;
    switch (stage) {
        case 0:  Z = g_h   + (sb&1)*65536; O = g_E64 + sb*65536; break;
        case 1:  Z = g_E64 + sb*65536;     O = g_F64 + sb*65536; break;
        case 2:  Z = g_rh  + (sb&1)*65536; O = g_G64 + sb*65536; break;
        default: Z = g_G64 + sb*65536;     O = g_H64 + sb*65536; break;
    }
    const float* A = adj + (size_t)sb*1048576 + (size_t)w0*1024;
    const int tid = threadIdx.x;

    __shared__ float Zs[2][32][36];
    __shared__ float As[2][32][66];

    const int zr = tid >> 3;          // 0..31 channel row in tile
    const int zv = (tid & 7) * 4;     // v offset (one float4)
    const int ar = tid >> 2;          // 0..63 w row
    const int av = (tid & 3) * 8;     // v offset (two float4s)

    const float* Zrow = Z + (size_t)(c0 + zr)*1024;
    const float* Arow = A + (size_t)ar*1024;

    float4 rz, ra0, ra1;
    rz  = *(const float4*)&Zrow[zv];
    ra0 = *(const float4*)&Arow[av];
    ra1 = *(const float4*)&Arow[av + 4];
    Zs[0][zv+0][zr] = rz.x;  Zs[0][zv+1][zr] = rz.y;
    Zs[0][zv+2][zr] = rz.z;  Zs[0][zv+3][zr] = rz.w;
    As[0][av+0][ar] = ra0.x; As[0][av+1][ar] = ra0.y;
    As[0][av+2][ar] = ra0.z; As[0][av+3][ar] = ra0.w;
    As[0][av+4][ar] = ra1.x; As[0][av+5][ar] = ra1.y;
    As[0][av+6][ar] = ra1.z; As[0][av+7][ar] = ra1.w;
    __syncthreads();

    const int cg = (tid >> 5) * 4;    // warp*4 : channel group (broadcast within warp)
    const int wl = (tid & 31) * 2;    // lane w pair
    float acc[4][2] = {};

    int buf = 0;
    for (int kt = 0; kt < 32; kt++) {
        if (kt < 31) {
            const int v0 = (kt + 1) * 32;
            rz  = *(const float4*)&Zrow[v0 + zv];
            ra0 = *(const float4*)&Arow[v0 + av];
            ra1 = *(const float4*)&Arow[v0 + av + 4];
        }
        #pragma unroll
        for (int k = 0; k < 32; k++) {
            float4 z = *(const float4*)&Zs[buf][k][cg];   // broadcast across warp
            float2 a = *(const float2*)&As[buf][k][wl];
            acc[0][0] += z.x*a.x; acc[0][1] += z.x*a.y;
            acc[1][0] += z.y*a.x; acc[1][1] += z.y*a.y;
            acc[2][0] += z.z*a.x; acc[2][1] += z.z*a.y;
            acc[3][0] += z.w*a.x; acc[3][1] += z.w*a.y;
        }
        if (kt < 31) {
            const int nb2 = buf ^ 1;
            Zs[nb2][zv+0][zr] = rz.x;  Zs[nb2][zv+1][zr] = rz.y;
            Zs[nb2][zv+2][zr] = rz.z;  Zs[nb2][zv+3][zr] = rz.w;
            As[nb2][av+0][ar] = ra0.x; As[nb2][av+1][ar] = ra0.y;
            As[nb2][av+2][ar] = ra0.z; As[nb2][av+3][ar] = ra0.w;
            As[nb2][av+4][ar] = ra1.x; As[nb2][av+5][ar] = ra1.y;
            As[nb2][av+6][ar] = ra1.z; As[nb2][av+7][ar] = ra1.w;
        }
        __syncthreads();
        buf ^= 1;
    }
    #pragma unroll
    for (int i = 0; i < 4; i++) {
        *(float2*)&O[(size_t)(c0+cg+i)*1024 + w0 + wl] = make_float2(acc[i][0], acc[i][1]);
    }
}

// =====================================================================================
// 2-channel diffusion. stage 0: z1->Dx  1: z2->Ex  2: Ex->Fx
// grid (128, 4), 256 threads: one w per warp, float4 lanes over v (MLP 8) + warp reduce.
// =====================================================================================
__global__ __launch_bounds__(256) void diffuse2_kernel(const float* __restrict__ adj, int stage)
{
    const int sb = blockIdx.y;
    __shared__ float zs[2][NB];
    const float* src;
    if      (stage == 0) src = g_z1 + (sb&1)*2048;
    else if (stage == 1) src = g_z2 + (sb&1)*2048;
    else                 src = g_Ex + sb*2048;
    for (int i = threadIdx.x; i < 2048; i += 256) zs[i >> 10][i & 1023] = src[i];
    __syncthreads();

    const int warp = threadIdx.x >> 5, lane = threadIdx.x & 31;
    const int w = blockIdx.x * 8 + warp;
    const float* Arow = adj + (size_t)sb*1048576 + (size_t)w*1024;
    float a0 = 0.f, a1 = 0.f;
    #pragma unroll
    for (int j = 0; j < 8; j++) {
        const int v = lane*4 + j*128;
        float4 av = *(const float4*)&Arow[v];
        float4 z0 = *(const float4*)&zs[0][v];
        float4 z1 = *(const float4*)&zs[1][v];
        a0 += av.x*z0.x + av.y*z0.y + av.z*z0.z + av.w*z0.w;
        a1 += av.x*z1.x + av.y*z1.y + av.z*z1.z + av.w*z1.w;
    }
    #pragma unroll
    for (int off = 16; off; off >>= 1) {
        a0 += __shfl_down_sync(0xffffffffu, a0, off);
        a1 += __shfl_down_sync(0xffffffffu, a1, off);
    }
    if (lane == 0) {
        float* dst;
        if      (stage == 0) dst = g_Dx + sb*2048;
        else if (stage == 1) dst = g_Ex + sb*2048;
        else                 dst = g_Fx + sb*2048;
        dst[w]        = a0;
        dst[1024 + w] = a1;
    }
}

// =====================================================================================
// pre kernel: xs1 = Wfs.h + bfs ; preds out ; x1 = m?x:xs1 ; z1 = [x1;m]
// 64 blocks x 256 threads; 8 threads per node (8-way c-split) + width-8 shfl reduce.
// =====================================================================================
__global__ __launch_bounds__(256) void pre_kernel(const float* __restrict__ x,
                                                  const int*   __restrict__ mask,
                                                  const float* __restrict__ Wfs,
                                                  const float* __restrict__ bfs,
                                                  float* __restrict__ out, int t)
{
    const int b   = blockIdx.x >> 5;
    const int tid = threadIdx.x;
    const int nl  = tid >> 3;             // 0..31 node within tile
    const int cg  = tid & 7;              // 0..7 channel group
    const int nn  = (blockIdx.x & 31) * 32 + nl;

    float s = 0.f;
    #pragma unroll
    for (int i = 0; i < 8; i++) {
        int c = cg * 8 + i;
        s += Wfs[c] * g_h[b*65536 + c*1024 + nn];
    }
    // reduce within each aligned 8-lane group
    s += __shfl_down_sync(0xffffffffu, s, 4, 8);
    s += __shfl_down_sync(0xffffffffu, s, 2, 8);
    s += __shfl_down_sync(0xffffffffu, s, 1, 8);
    if (cg == 0) {
        s += bfs[0];
        out[PRED_OFF + (b*1024 + nn)*12 + t] = s;
        int m = mask[b*12288 + nn*12 + t];
        float xv = x[b*12288 + nn*12 + t];
        float x1 = m ? xv : s;
        g_z1[b*2048 + nn]        = x1;
        g_z1[b*2048 + 1024 + nn] = (float)m;
    }
}

// =====================================================================================
// decoder (16-wide n-tiles, 128 blocks):
//   out = M0.[Dx0;E0] + M1.[Dx1;E1] + vb0*rs0 + vb1*rs1 + bgc
//   out = prelu(Wlout.[out;h]+blout) ; repr=[out;h] ; xs2=Wro.repr+bro
//   imps out ; z2 = [m?x1:xs2 ; m]
// =====================================================================================
__global__ __launch_bounds__(256) void decoder_kernel(const float* __restrict__ bgc,
                                                      const float* __restrict__ blout,
                                                      const float* __restrict__ Wro,
                                                      const float* __restrict__ bro,
                                                      const float* __restrict__ prelu_a,
                                                      const int*   __restrict__ mask,
                                                      float* __restrict__ out, int t)
{
    const int b  = blockIdx.x >> 6;
    const int n0 = (blockIdx.x & 63) * 16;
    const int tid = threadIdx.x;
    __shared__ float E0s[64][17];
    __shared__ float E1s[64][17];
    __shared__ float Hs[64][17];
    __shared__ float Gs[64][17];
    __shared__ float Os[64][17];
    __shared__ float DXs[2][2][17];
    __shared__ float RSs[2][17];

    for (int i = tid; i < 64*16; i += 256) {
        int r = i >> 4, n = i & 15;
        E0s[r][n] = g_E64[b*65536     + r*1024 + n0 + n];
        E1s[r][n] = g_E64[(2+b)*65536 + r*1024 + n0 + n];
        Hs[r][n]  = g_h  [b*65536     + r*1024 + n0 + n];
    }
    if (tid < 64) {
        int s = tid >> 5, ch = (tid >> 4) & 1, n = tid & 15;
        DXs[s][ch][n] = g_Dx[(s*2 + b)*2048 + ch*1024 + n0 + n];
    } else if (tid < 96) {
        int idx = tid - 64; int s = idx >> 4, n = idx & 15;
        RSs[s][n] = g_rs[(s*2 + b)*1024 + n0 + n];
    }
    __syncthreads();

    const int ty = tid >> 4, tx = tid & 15;
    const int cbv = ty*4;
    float acc[4] = {};
    #pragma unroll
    for (int s = 0; s < 2; s++) {
        const float* Mt = g_M_t + s*66*64;
        {
            float4 w0 = *(const float4*)&Mt[0*64 + cbv];
            float v0 = DXs[s][0][tx];
            acc[0] += w0.x*v0; acc[1] += w0.y*v0; acc[2] += w0.z*v0; acc[3] += w0.w*v0;
            float4 w1 = *(const float4*)&Mt[1*64 + cbv];
            float v1 = DXs[s][1][tx];
            acc[0] += w1.x*v1; acc[1] += w1.y*v1; acc[2] += w1.z*v1; acc[3] += w1.w*v1;
        }
        #pragma unroll 4
        for (int k = 0; k < 64; k++) {
            float4 w = *(const float4*)&Mt[(2+k)*64 + cbv];
            float v = s ? E1s[k][tx] : E0s[k][tx];
            acc[0] += w.x*v; acc[1] += w.y*v; acc[2] += w.z*v; acc[3] += w.w*v;
        }
    }
    #pragma unroll
    for (int i = 0; i < 4; i++) {
        int c = cbv + i;
        Gs[c][tx] = acc[i] + g_vb[c]*RSs[0][tx] + g_vb[64+c]*RSs[1][tx] + bgc[c];
    }
    __syncthreads();

    float acc2[4] = {};
    #pragma unroll 4
    for (int k = 0; k < 64; k++) {
        float4 w = *(const float4*)&g_Wlout_t[k*64 + cbv];
        float v = Gs[k][tx];
        acc2[0] += w.x*v; acc2[1] += w.y*v; acc2[2] += w.z*v; acc2[3] += w.w*v;
    }
    #pragma unroll 4
    for (int k = 0; k < 64; k++) {
        float4 w = *(const float4*)&g_Wlout_t[(64+k)*64 + cbv];
        float v = Hs[k][tx];
        acc2[0] += w.x*v; acc2[1] += w.y*v; acc2[2] += w.z*v; acc2[3] += w.w*v;
    }
    const float pa = prelu_a[0];
    #pragma unroll
    for (int i = 0; i < 4; i++) {
        int c = cbv + i;
        float o = acc2[i] + blout[c]; if (o < 0.f) o *= pa;
        Os[c][tx] = o;
        g_rep[((size_t)(t*2 + b)*128 + c)*1024 + n0 + tx] = o;
    }
    __syncthreads();

    for (int i = tid; i < 64*16; i += 256) {
        int c = i >> 4, n = i & 15;
        g_rep[((size_t)(t*2 + b)*128 + 64 + c)*1024 + n0 + n] = Hs[c][n];
    }
    if (tid < 16) {
        const int n = tid, nn = n0 + n;
        float s = bro[0];
        #pragma unroll 8
        for (int c = 0; c < 64; c++) s += Wro[c]*Os[c][n] + Wro[64+c]*Hs[c][n];
        out[IMP_OFF + (b*1024 + nn)*12 + t] = s;
        int m = mask[b*12288 + nn*12 + t];
        float x2 = m ? g_z1[b*2048 + nn] : s;
        g_z2[b*2048 + nn]        = x2;
        g_z2[b*2048 + 1024 + nn] = (float)m;
    }
}

// =====================================================================================
// V330 loader (16-wide n-tile). base64: h or rh.
// Row map (330): [z2(2), base64(64)] , per support s: [ex(2), d1(64), fx(2), d2(64)]
// =====================================================================================
__device__ __forceinline__ void load_V330_16(float (*Vs)[17], int b, int n0, int tid,
                                             const float* base64)
{
    for (int i = tid; i < 330*16; i += 256) {
        int r = i >> 4, n = i & 15;
        const float* src;
        const int sb0 = b, sb1 = 2 + b;
        if      (r < 2)   src = g_z2   + b*2048    + r*1024;
        else if (r < 66)  src = base64 + b*65536   + (r-2)*1024;
        else if (r < 68)  src = g_Ex   + sb0*2048  + (r-66)*1024;
        else if (r < 132) src = (base64 == g_h ? g_E64 : g_G64) + sb0*65536 + (r-68)*1024;
        else if (r < 134) src = g_Fx   + sb0*2048  + (r-132)*1024;
        else if (r < 198) src = (base64 == g_h ? g_F64 : g_H64) + sb0*65536 + (r-134)*1024;
        else if (r < 200) src = g_Ex   + sb1*2048  + (r-198)*1024;
        else if (r < 264) src = (base64 == g_h ? g_E64 : g_G64) + sb1*65536 + (r-200)*1024;
        else if (r < 266) src = g_Fx   + sb1*2048  + (r-264)*1024;
        else              src = (base64 == g_h ? g_F64 : g_H64) + sb1*65536 + (r-266)*1024;
        Vs[r][n] = src[n0 + n];
    }
}

__global__ __launch_bounds__(256) void gates_kernel(const float* __restrict__ br,
                                                    const float* __restrict__ bu)
{
    const int b  = blockIdx.x >> 6;
    const int n0 = (blockIdx.x & 63) * 16;
    const int tid = threadIdx.x;
    __shared__ float Vs[330][17];
    load_V330_16(Vs, b, n0, tid, g_h);
    __syncthreads();

    const int ty = tid >> 4, tx = tid & 15;
    const int cbv = ty*4;
    float ar4[4] = {}, au4[4] = {};
    #pragma unroll 5
    for (int k = 0; k < 330; k++) {
        float4 wr = *(const float4*)&g_Wr_t[k*64 + cbv];
        float4 wu = *(const float4*)&g_Wu_t[k*64 + cbv];
        float v = Vs[k][tx];
        ar4[0] += wr.x*v; ar4[1] += wr.y*v; ar4[2] += wr.z*v; ar4[3] += wr.w*v;
        au4[0] += wu.x*v; au4[1] += wu.y*v; au4[2] += wu.z*v; au4[3] += wu.w*v;
    }
    #pragma unroll
    for (int i = 0; i < 4; i++) {
        const int c = cbv + i;
        const size_t idx = (size_t)b*65536 + c*1024 + n0 + tx;
        float hv = g_h[idx];
        float r = 1.f / (1.f + expf(-(ar4[i] + br[c])));
        float u = 1.f / (1.f + expf(-(au4[i] + bu[c])));
        g_u [idx] = u;
        g_rh[idx] = r * hv;
    }
}

__global__ __launch_bounds__(256) void cand_kernel(const float* __restrict__ bc)
{
    const int b  = blockIdx.x >> 6;
    const int n0 = (blockIdx.x & 63) * 16;
    const int tid = threadIdx.x;
    __shared__ float Vs[330][17];
    load_V330_16(Vs, b, n0, tid, g_rh);
    __syncthreads();

    const int ty = tid >> 4, tx = tid & 15;
    const int cbv = ty*4;
    float acc4[4] = {};
    #pragma unroll 5
    for (int k = 0; k < 330; k++) {
        float4 w = *(const float4*)&g_Wc_t[k*64 + cbv];
        float v = Vs[k][tx];
        acc4[0] += w.x*v; acc4[1] += w.y*v; acc4[2] += w.z*v; acc4[3] += w.w*v;
    }
    #pragma unroll
    for (int i = 0; i < 4; i++) {
        const int c = cbv + i;
        const size_t idx = (size_t)b*65536 + c*1024 + n0 + tx;
        float hv = g_h[idx];
        float uv = g_u[idx];
        float cv = tanhf(acc4[i] + bc[c]);
        g_h[idx] = uv*hv + (1.f-uv)*cv;
    }
}

// Final transpose of staged representations: out[b][cc][n][t] = g_rep[t][b][cc][n]
__global__ __launch_bounds__(256) void rep_out_kernel(float* __restrict__ out)
{
    const int bc = blockIdx.x;               // 0..255 = b*128+cc
    const int b = bc >> 7, cc = bc & 127;
    __shared__ float s[12][NB];
    for (int i = threadIdx.x; i < 12*NB; i += 256) {
        int t = i >> 10, n = i & 1023;
        s[t][n] = g_rep[((size_t)(t*2 + b)*128 + cc)*1024 + n];
    }
    __syncthreads();
    float* dst = out + REP_OFF + (size_t)bc * 12288;
    for (int i = threadIdx.x; i < 12288; i += 256) {
        int n = i / 12, t = i - n*12;
        dst[i] = s[t][n];
    }
}

extern "C" void kernel_launch(void* const* d_in, const int* in_sizes, int n_in,
                              void* d_out, int out_size)
{
    const float* x     = (const float*)d_in[0];
    const int*   mask  = (const int*)  d_in[1];
    const float* adj   = (const float*)d_in[2];
    const float* Wr    = (const float*)d_in[3];
    const float* br    = (const float*)d_in[4];
    const float* Wu    = (const float*)d_in[5];
    const float* bu    = (const float*)d_in[6];
    const float* Wc    = (const float*)d_in[7];
    const float* bc    = (const float*)d_in[8];
    const float* Wfs   = (const float*)d_in[9];
    const float* bfs   = (const float*)d_in[10];
    const float* Wdin  = (const float*)d_in[11];
    const float* bdin  = (const float*)d_in[12];
    const float* Wgc   = (const float*)d_in[13];
    const float* bgc   = (const float*)d_in[14];
    const float* Wlout = (const float*)d_in[15];
    const float* blout = (const float*)d_in[16];
    const float* Wro   = (const float*)d_in[17];
    const float* bro   = (const float*)d_in[18];
    const float* pa    = (const float*)d_in[19];
    float* out = (float*)d_out;

    init_h_kernel<<<512, 256>>>();
    prep_weights_kernel<<<83, 256>>>(Wr, Wu, Wc, Wlout);
    prep_M_kernel<<<dim3(17,2), 256>>>(Wgc, Wdin, bdin);

    for (int t = 0; t < 12; t++) {
        pre_kernel<<<64, 256>>>(x, mask, Wfs, bfs, out, t);
        diffuse2_kernel<<<dim3(128,4), 256>>>(adj, 0);          // Dx
        diffuse64_kernel<<<dim3(16,2,4), 256>>>(adj, 0);        // E = A h
        diffuse64_kernel<<<dim3(16,2,4), 256>>>(adj, 1);        // F = A E
        if (t == 0) rowsum_kernel<<<dim3(128,4), 256>>>(adj);   // loop-invariant
        decoder_kernel<<<128, 256>>>(bgc, blout, Wro, bro, pa, mask, out, t);
        diffuse2_kernel<<<dim3(128,4), 256>>>(adj, 1);          // Ex
        diffuse2_kernel<<<dim3(128,4), 256>>>(adj, 2);          // Fx
        gates_kernel<<<128, 256>>>(br, bu);
        diffuse64_kernel<<<dim3(16,2,4), 256>>>(adj, 2);        // G = A rh
        diffuse64_kernel<<<dim3(16,2,4), 256>>>(adj, 3);        // H = A G
        cand_kernel<<<128, 256>>>(bc);
    }
    rep_out_kernel<<<256, 256>>>(out);
}